// round 11
// baseline (speedup 1.0000x reference)
#include <cuda_runtime.h>
#include <cuda_fp16.h>
#include <cstdint>
#include <cstddef>
#include <cstring>

#define NNODES 10000
#define NEDGES 640000
#define HID    128
#define OUTD   10

// Scratch (fp16): PQ[n][0:128]   = fp16( x[n] @ W1[0:128,:] )        (P)
//                 PQ[n][128:256] = fp16( x[n] @ W1[128:256,:] + b1 )  (Q')
__device__ __half g_PQh[NNODES * 256];

// ---------- packed f32x2 helpers ----------
__device__ __forceinline__ unsigned long long f2_pack1(float v) {
    unsigned long long d;
    unsigned int u = __float_as_uint(v);
    asm("mov.b64 %0, {%1, %2};" : "=l"(d) : "r"(u), "r"(u));
    return d;
}
__device__ __forceinline__ unsigned long long f2_make(float a, float b) {
    unsigned long long d;
    unsigned int ua = __float_as_uint(a), ub = __float_as_uint(b);
    asm("mov.b64 %0, {%1, %2};" : "=l"(d) : "r"(ua), "r"(ub));
    return d;
}
__device__ __forceinline__ unsigned long long f2_fma(unsigned long long a,
                                                     unsigned long long b,
                                                     unsigned long long c) {
    unsigned long long d;
    asm("fma.rn.f32x2 %0, %1, %2, %3;" : "=l"(d) : "l"(a), "l"(b), "l"(c));
    return d;
}
__device__ __forceinline__ unsigned long long f2_add(unsigned long long a,
                                                     unsigned long long b) {
    unsigned long long d;
    asm("add.rn.f32x2 %0, %1, %2;" : "=l"(d) : "l"(a), "l"(b));
    return d;
}
__device__ __forceinline__ void f2_unpack(unsigned long long v, float& lo, float& hi) {
    unsigned int a, b;
    asm("mov.b64 {%0, %1}, %2;" : "=r"(a), "=r"(b) : "l"(v));
    lo = __uint_as_float(a);
    hi = __uint_as_float(b);
}
__device__ __forceinline__ unsigned h2_bits(__half2 h) {
    unsigned u;
    memcpy(&u, &h, 4);
    return u;
}

// ============================================================================
// Phase 1: PQ = fp16( x @ [W1a | W1b] ), b1 folded into the Q half.
// M=10000, N=256, K=128. BM=BN=BK=64; 256 threads; 4x4 per thread.
// As stored TRANSPOSED (k-major) so mainloop a-loads are LDS.128;
// accumulation in packed f32x2 (8 FFMA2 per k-step).
// ============================================================================
__global__ void __launch_bounds__(256) phase1_kernel(const float* __restrict__ x,
                                                     const float* __restrict__ W1,
                                                     const float* __restrict__ b1) {
    __shared__ float At[64][68];   // [k][m] transposed
    __shared__ float Bs[64][68];   // [k][n]

    const int tid = threadIdx.x;
    const int m0 = blockIdx.x * 64;
    const int n0 = blockIdx.y * 64;
    const int tr = (tid >> 4) << 2;
    const int tc = (tid & 15) << 2;

    const int wRow = (n0 < 128) ? 0 : 128;
    const int wCol = (n0 < 128) ? n0 : (n0 - 128);

    unsigned long long acc[4][2] = {};   // 4 rows x (2 packed f32x2 = 4 cols)

    for (int k0 = 0; k0 < 128; k0 += 64) {
        // Load A tile transposed: thread reads float4 (m, k..k+3), scatters 4 STS.32
        #pragma unroll
        for (int i = 0; i < 4; i++) {
            int idx = tid + i * 256;
            int m = idx >> 4, kq = idx & 15;
            int gm = m0 + m;
            float4 v = make_float4(0.f, 0.f, 0.f, 0.f);
            if (gm < NNODES) v = *(const float4*)(x + (size_t)gm * HID + k0 + kq * 4);
            At[kq * 4 + 0][m] = v.x;
            At[kq * 4 + 1][m] = v.y;
            At[kq * 4 + 2][m] = v.z;
            At[kq * 4 + 3][m] = v.w;
        }
        #pragma unroll
        for (int i = 0; i < 4; i++) {
            int idx = tid + i * 256;
            int kk = idx >> 4, cq = idx & 15;
            float4 v = *(const float4*)(W1 + (size_t)(k0 + kk + wRow) * HID + wCol + cq * 4);
            *(float4*)&Bs[kk][cq * 4] = v;
        }
        __syncthreads();

        #pragma unroll
        for (int k = 0; k < 64; k++) {
            float4 a = *(const float4*)&At[k][tr];
            float4 b = *(const float4*)&Bs[k][tc];
            unsigned long long b01 = f2_make(b.x, b.y);
            unsigned long long b23 = f2_make(b.z, b.w);
            unsigned long long a0 = f2_pack1(a.x);
            unsigned long long a1 = f2_pack1(a.y);
            unsigned long long a2 = f2_pack1(a.z);
            unsigned long long a3 = f2_pack1(a.w);
            acc[0][0] = f2_fma(a0, b01, acc[0][0]);
            acc[0][1] = f2_fma(a0, b23, acc[0][1]);
            acc[1][0] = f2_fma(a1, b01, acc[1][0]);
            acc[1][1] = f2_fma(a1, b23, acc[1][1]);
            acc[2][0] = f2_fma(a2, b01, acc[2][0]);
            acc[2][1] = f2_fma(a2, b23, acc[2][1]);
            acc[3][0] = f2_fma(a3, b01, acc[3][0]);
            acc[3][1] = f2_fma(a3, b23, acc[3][1]);
        }
        __syncthreads();
    }

    // Fold b1 into Q half; convert to fp16; store 4 halves (STG.64) per row
    float4 bv = make_float4(0.f, 0.f, 0.f, 0.f);
    if (n0 >= 128) bv = *(const float4*)(b1 + wCol + tc);

    #pragma unroll
    for (int r = 0; r < 4; r++) {
        int gm = m0 + tr + r;
        if (gm < NNODES) {
            float c0, c1, c2, c3;
            f2_unpack(acc[r][0], c0, c1);
            f2_unpack(acc[r][1], c2, c3);
            __half2 h0 = __floats2half2_rn(c0 + bv.x, c1 + bv.y);
            __half2 h1 = __floats2half2_rn(c2 + bv.z, c3 + bv.w);
            uint2 pk;
            pk.x = h2_bits(h0);
            pk.y = h2_bits(h1);
            *(uint2*)(g_PQh + (size_t)gm * 256 + n0 + tc) = pk;
        }
    }
}

// ============================================================================
// Phase 2 v7: fp16 PQ gather (4 wf/edge) + register W2 + trimmed shfl tree.
// Warp = 2 edges: half h = lane>>4, t = lane&15.
// Lane t loads uint4 = 8 halves of P (j=8t..8t+7) and 8 halves of Q (same j)
// -> 2 LDG.128 per 2 edges (4 wavefronts/edge).
// h_j = relu(p+q) in fp16 (HADD2+HMAX2), converted to f32 for FFMA2 vs
// register-resident W2 rows 8t..8t+7 (40 u64).
// Reduce per 16-lane half: a0-a3 full u64 tree xor8,xor4; select pair c=t>>2;
// xor2,xor1 on r. a4 split to scalars at level 1 (o8 -> t<8, o9 -> t>=8).
// 24 SHFL.32 per 2 edges. b2 folded into lane t==0 acc init.
// ============================================================================
#define P2_THREADS 256
#define P2_ITERS 32
// edges/block = 8 warps * 32 iters * 2 = 512; grid = 1250

__global__ void __launch_bounds__(P2_THREADS, 2)
phase2_kernel(const int* __restrict__ ei,
              const float* __restrict__ W2,
              const float* __restrict__ b2,
              float* __restrict__ out) {
    const int tid  = threadIdx.x;
    const int lane = tid & 31;
    const int h    = lane >> 4;
    const int t    = lane & 15;
    const int c    = t >> 2;

    // Lane's W2 slice (rows 8t..8t+7) in registers
    unsigned long long w[8][5];
    #pragma unroll
    for (int i = 0; i < 8; i++) {
        const float* wr = W2 + (8 * t + i) * OUTD;
        #pragma unroll
        for (int o2 = 0; o2 < 5; o2++)
            w[i][o2] = f2_make(wr[2 * o2], wr[2 * o2 + 1]);
    }

    // b2 folded into init accs on lane t==0 (counts once in the 16-lane sum)
    const bool lz = (t == 0);
    const unsigned long long i0 = lz ? f2_make(b2[0], b2[1]) : 0ull;
    const unsigned long long i1 = lz ? f2_make(b2[2], b2[3]) : 0ull;
    const unsigned long long i2 = lz ? f2_make(b2[4], b2[5]) : 0ull;
    const unsigned long long i3 = lz ? f2_make(b2[6], b2[7]) : 0ull;
    const unsigned long long i4 = lz ? f2_make(b2[8], b2[9]) : 0ull;

    const int e0 = blockIdx.x * 512 + (tid >> 5) * (P2_ITERS * 2);
    const uint4* __restrict__ PQ4 = (const uint4*)g_PQh;   // 32 uint4 per node row

    // Prologue gather (edge e0+h): P uint4 t, Q uint4 16+t
    int src = ei[e0 + h];
    int dst = ei[NEDGES + e0 + h];
    uint4 pv = PQ4[(size_t)src * 32 + t];
    uint4 qv = PQ4[(size_t)dst * 32 + 16 + t];

    for (int it = 0; it < P2_ITERS; it++) {
        const int e = e0 + it * 2 + h;

        // h = relu(p + q) in fp16, then upconvert to 8 f32
        const __half2 z2 = __float2half2_rn(0.f);
        __half2 ph0 = *(__half2*)&pv.x, ph1 = *(__half2*)&pv.y;
        __half2 ph2 = *(__half2*)&pv.z, ph3 = *(__half2*)&pv.w;
        __half2 qh0 = *(__half2*)&qv.x, qh1 = *(__half2*)&qv.y;
        __half2 qh2 = *(__half2*)&qv.z, qh3 = *(__half2*)&qv.w;
        __half2 h0 = __hmax2(__hadd2(ph0, qh0), z2);
        __half2 h1 = __hmax2(__hadd2(ph1, qh1), z2);
        __half2 h2 = __hmax2(__hadd2(ph2, qh2), z2);
        __half2 h3 = __hmax2(__hadd2(ph3, qh3), z2);
        float2 f0 = __half22float2(h0);
        float2 f1 = __half22float2(h1);
        float2 f2v = __half22float2(h2);
        float2 f3 = __half22float2(h3);
        float hv[8] = { f0.x, f0.y, f1.x, f1.y, f2v.x, f2v.y, f3.x, f3.y };

        // Prefetch next edge's rows (pv/qv dead now)
        if (it + 1 < P2_ITERS) {
            src = ei[e0 + (it + 1) * 2 + h];
            dst = ei[NEDGES + e0 + (it + 1) * 2 + h];
            pv = PQ4[(size_t)src * 32 + t];
            qv = PQ4[(size_t)dst * 32 + 16 + t];
        }

        unsigned long long a0 = i0, a1 = i1, a2 = i2, a3 = i3, a4 = i4;
        #pragma unroll
        for (int i = 0; i < 8; i++) {
            unsigned long long vv = f2_pack1(hv[i]);
            a0 = f2_fma(vv, w[i][0], a0);
            a1 = f2_fma(vv, w[i][1], a1);
            a2 = f2_fma(vv, w[i][2], a2);
            a3 = f2_fma(vv, w[i][3], a3);
            a4 = f2_fma(vv, w[i][4], a4);
        }

        // ---- reduce over the 16-lane half ----
        // a4 -> scalar split at level 1: t<8 accumulates o8, t>=8 o9
        float s8, s9;
        f2_unpack(a4, s8, s9);
        float gsend = (t < 8) ? s9 : s8;
        float gkeep = (t < 8) ? s8 : s9;
        float g = gkeep + __shfl_xor_sync(0xFFFFFFFFu, gsend, 8);

        a0 = f2_add(a0, __shfl_xor_sync(0xFFFFFFFFu, a0, 8));
        a1 = f2_add(a1, __shfl_xor_sync(0xFFFFFFFFu, a1, 8));
        a2 = f2_add(a2, __shfl_xor_sync(0xFFFFFFFFu, a2, 8));
        a3 = f2_add(a3, __shfl_xor_sync(0xFFFFFFFFu, a3, 8));

        g += __shfl_xor_sync(0xFFFFFFFFu, g, 4);
        a0 = f2_add(a0, __shfl_xor_sync(0xFFFFFFFFu, a0, 4));
        a1 = f2_add(a1, __shfl_xor_sync(0xFFFFFFFFu, a1, 4));
        a2 = f2_add(a2, __shfl_xor_sync(0xFFFFFFFFu, a2, 4));
        a3 = f2_add(a3, __shfl_xor_sync(0xFFFFFFFFu, a3, 4));

        // lane's quad owns out-pair c
        unsigned long long r = (c & 2) ? ((c & 1) ? a3 : a2)
                                       : ((c & 1) ? a1 : a0);
        r = f2_add(r, __shfl_xor_sync(0xFFFFFFFFu, r, 2));
        g += __shfl_xor_sync(0xFFFFFFFFu, g, 2);
        r = f2_add(r, __shfl_xor_sync(0xFFFFFFFFu, r, 1));
        g += __shfl_xor_sync(0xFFFFFFFFu, g, 1);

        if ((t & 3) == 0) {
            float lo, hi;
            f2_unpack(r, lo, hi);
            *(float2*)(out + (size_t)e * OUTD + 2 * c) = make_float2(lo, hi);
        }
        if (t == 1) out[(size_t)e * OUTD + 8] = g;
        if (t == 9) out[(size_t)e * OUTD + 9] = g;
    }
}

// ============================================================================
extern "C" void kernel_launch(void* const* d_in, const int* in_sizes, int n_in,
                              void* d_out, int out_size) {
    const float* x  = (const float*)d_in[0];
    const int*   ei = (const int*)d_in[1];
    const float* W1 = (const float*)d_in[2];
    const float* b1 = (const float*)d_in[3];
    const float* W2 = (const float*)d_in[4];
    const float* b2 = (const float*)d_in[5];
    float* out = (float*)d_out;

    dim3 g1((NNODES + 63) / 64, 256 / 64);
    phase1_kernel<<<g1, 256>>>(x, W1, b1);

    phase2_kernel<<<1250, P2_THREADS>>>(ei, W2, b2, out);
}